// round 2
// baseline (speedup 1.0000x reference)
#include <cuda_runtime.h>
#include <math.h>
#include <stdint.h>

#define BATCH 512
#define NGEN  4095
#define QDIM  64

// ------------------- scratch (static device globals; no allocs) -------------
__device__ float  g_h[BATCH * 256];        // hidden after enc layer 1
__device__ float  g_theta[BATCH * 4096];   // angles (row stride 4096)
__device__ float  g_W2p[256 * 4096];       // padded W2
__device__ float2 g_H[BATCH * 4096];       // H_eff per batch, row-major 64x64
__device__ float  g_q[BATCH * 16];         // 15 expectations
__device__ float  g_h2[BATCH * 256];       // hidden of vel head

__constant__ int c_wa[15] = {0,0,0,0,0,1,1,1,1,2,2,2,3,3,4};
__constant__ int c_wb[15] = {1,2,3,4,5,2,3,4,5,3,4,5,4,5,5};

__device__ __forceinline__ float silu_f(float x) { return x / (1.f + expf(-x)); }

// ------------------- pad W2 (256 x 4095 -> 256 x 4096) ----------------------
__global__ void k_pad(const float* __restrict__ W2) {
    int idx = blockIdx.x * blockDim.x + threadIdx.x;
    if (idx < 256 * 4096) {
        int col = idx & 4095;
        int row = idx >> 12;
        g_W2p[idx] = (col < NGEN) ? W2[row * NGEN + col] : 0.f;
    }
}

// ------------------- tiled SGEMM: C = act(A*B + bias) -----------------------
// BM=BN=64, BK=16, 256 threads, 4x4 per-thread tile.
// M,N implied by grid (multiples of 64). K % 16 == 0, lda/ldb/ldc % 4 == 0.
__global__ void sgemm64(const float* __restrict__ A, const float* __restrict__ B,
                        float* __restrict__ C, int K, int lda, int ldb, int ldc,
                        const float* __restrict__ bias, int nbias, int act)
{
    __shared__ float As[16][64];
    __shared__ float Bs[16][64];
    int tid = threadIdx.x;
    int bm = blockIdx.y * 64, bn = blockIdx.x * 64;
    int tx = tid & 15, ty = tid >> 4;

    int arow = tid >> 2;
    int akq  = (tid & 3) * 4;
    int brow = tid >> 4;
    int bcol = (tid & 15) * 4;

    float acc[4][4] = {};

    for (int k0 = 0; k0 < K; k0 += 16) {
        float4 av = *reinterpret_cast<const float4*>(A + (size_t)(bm + arow) * lda + k0 + akq);
        float4 bv = *reinterpret_cast<const float4*>(B + (size_t)(k0 + brow) * ldb + bn + bcol);
        As[akq + 0][arow] = av.x;
        As[akq + 1][arow] = av.y;
        As[akq + 2][arow] = av.z;
        As[akq + 3][arow] = av.w;
        *reinterpret_cast<float4*>(&Bs[brow][bcol]) = bv;
        __syncthreads();
#pragma unroll
        for (int k = 0; k < 16; k++) {
            float4 a = *reinterpret_cast<float4*>(&As[k][ty * 4]);
            float4 bq = *reinterpret_cast<float4*>(&Bs[k][tx * 4]);
            float ar[4] = {a.x, a.y, a.z, a.w};
            float br[4] = {bq.x, bq.y, bq.z, bq.w};
#pragma unroll
            for (int i = 0; i < 4; i++)
#pragma unroll
                for (int j = 0; j < 4; j++)
                    acc[i][j] += ar[i] * br[j];
        }
        __syncthreads();
    }

#pragma unroll
    for (int i = 0; i < 4; i++) {
        int row = bm + ty * 4 + i;
        int col = bn + tx * 4;
        float o[4];
#pragma unroll
        for (int j = 0; j < 4; j++) {
            float v = acc[i][j];
            int cj = col + j;
            v += (cj < nbias) ? bias[cj] : 0.f;
            if (act) v = silu_f(v);
            o[j] = v;
        }
        *reinterpret_cast<float4*>(&C[(size_t)row * ldc + col]) =
            make_float4(o[0], o[1], o[2], o[3]);
    }
}

// ------------------- build H_eff from theta ---------------------------------
// H[i][j] = sum over 64 Pauli words compatible with d=i^j of theta[m]*phase.
__device__ __forceinline__ int sp2(int x) {
    return (x & 1) | ((x & 2) << 1) | ((x & 4) << 2) |
           ((x & 8) << 3) | ((x & 16) << 4) | ((x & 32) << 5);
}

__global__ void k_buildH() {
    __shared__ float th[4096];
    int b = blockIdx.x, t = threadIdx.x;
    for (int i = t; i < NGEN; i += 256) th[i] = g_theta[(size_t)b * 4096 + i];
    __syncthreads();
    for (int e = t; e < 4096; e += 256) {
        int i = e >> 6, j = e & 63, d = i ^ j;
        int spd = sp2(d);
        float re = 0.f, im = 0.f;
        int sel0 = (d == 0) ? 1 : 0;  // skip identity word
        for (int sel = sel0; sel < 64; ++sel) {
            int m = spd + sp2(sel & d) + 3 * sp2(sel & ~d & 63);
            float v = th[m - 1];
            int nY = __popc(sel & d);
            int sgn = (__popc(sel & d & ~i) + __popc(sel & (~d) & i) + (nY >> 1)) & 1;
            v = sgn ? -v : v;
            if (nY & 1) im += v; else re += v;
        }
        g_H[(size_t)b * 4096 + e] = make_float2(re, im);
    }
}

// ------------------- expm(iH)e0 + 2-local expectations ----------------------
// 128 threads: thread t = (row = t>>1, half = t&1) owns 32 complex of its row.
__global__ void __launch_bounds__(128) k_expm(const float* __restrict__ Aoff,
                                              const float* __restrict__ Boff,
                                              const float* __restrict__ Ddiag)
{
    int b = blockIdx.x, tid = threadIdx.x;
    int row = tid >> 1, half = tid & 1;
    __shared__ float2 ts[2][64];
    __shared__ float2 ps[64];
    __shared__ float  red[4];
    __shared__ int    sh_s;
    __shared__ float  sh_sc;

    // load half-row of H into registers (contiguous 256B per thread)
    float2 h[32];
    const float4* src = reinterpret_cast<const float4*>(&g_H[(size_t)b * 4096 + tid * 32]);
    float fr = 0.f;
#pragma unroll
    for (int c = 0; c < 16; c++) {
        float4 v = src[c];
        h[2 * c]     = make_float2(v.x, v.y);
        h[2 * c + 1] = make_float2(v.z, v.w);
        fr += v.x * v.x + v.y * v.y + v.z * v.z + v.w * v.w;
    }
#pragma unroll
    for (int o = 16; o; o >>= 1) fr += __shfl_xor_sync(0xffffffffu, fr, o);
    if ((tid & 31) == 0) red[tid >> 5] = fr;
    __syncthreads();
    if (tid == 0) {
        float fro = sqrtf(red[0] + red[1] + red[2] + red[3]);  // >= ||H||_2
        int e = 0;
        while (fro > 2.f && e < 14) { fro *= 0.5f; e++; }
        sh_s = e;
        sh_sc = ldexpf(1.f, -e);
    }
    __syncthreads();
    int S = sh_s;
    float sc = sh_sc;

    float2 vr = make_float2(0.f, 0.f), wr = make_float2(0.f, 0.f);
    if (row == 0 && half == 0) vr.x = 1.f;  // e0

    int nstep = 1 << S;
    for (int step = 0; step < nstep; ++step) {
        if (half == 0) { wr = vr; ts[0][row] = vr; }
        __syncthreads();
        int cur = 0;
#pragma unroll 1
        for (int n = 1; n <= 16; ++n) {
            float ux = 0.f, uy = 0.f;
            const float4* tp = reinterpret_cast<const float4*>(&ts[cur][half * 32]);
#pragma unroll
            for (int c = 0; c < 16; c++) {
                float4 t4 = tp[c];
                float2 a = h[2 * c];
                ux += a.x * t4.x - a.y * t4.y;
                uy += a.x * t4.y + a.y * t4.x;
                a = h[2 * c + 1];
                ux += a.x * t4.z - a.y * t4.w;
                uy += a.x * t4.w + a.y * t4.z;
            }
            ux += __shfl_xor_sync(0xffffffffu, ux, 1);
            uy += __shfl_xor_sync(0xffffffffu, uy, 1);
            if (half == 0) {
                float f = __fdividef(sc, (float)n);
                float2 tn = make_float2(-uy * f, ux * f);  // (i*u)*f
                wr.x += tn.x; wr.y += tn.y;
                ts[cur ^ 1][row] = tn;
            }
            __syncthreads();
            cur ^= 1;
        }
        if (half == 0) vr = wr;
    }
    if (half == 0) ps[row] = vr;  // psi
    __syncthreads();

    // 15 two-local expectations, one thread each (tiny)
    if (tid < 15) {
        int wa = c_wa[tid], wb = c_wb[tid];
        int pa = 5 - wa, pb = 5 - wb;
        float2 rho[4][4];
#pragma unroll
        for (int k = 0; k < 4; k++)
#pragma unroll
            for (int l = 0; l < 4; l++) rho[k][l] = make_float2(0.f, 0.f);

        for (int r = 0; r < 16; r++) {
            int base = 0, t = 3;
            for (int p = 5; p >= 0; --p) {
                if (p == pa || p == pb) continue;
                if ((r >> t) & 1) base |= 1 << p;
                t--;
            }
            float2 pv[4];
#pragma unroll
            for (int k = 0; k < 4; k++) {
                int p = base | ((k >> 1) << pa) | ((k & 1) << pb);
                pv[k] = ps[p];
            }
#pragma unroll
            for (int k = 0; k < 4; k++)
#pragma unroll
                for (int l = 0; l < 4; l++) {
                    // rho[k][l] += pv[k] * conj(pv[l])
                    rho[k][l].x += pv[k].x * pv[l].x + pv[k].y * pv[l].y;
                    rho[k][l].y += pv[k].y * pv[l].x - pv[k].x * pv[l].y;
                }
        }
        // q = Re tr(rho * Hw) with Hw per reference create_Hermitian
        float q = 2.f * (rho[0][0].x * Ddiag[tid * 4 + 1] +
                         rho[1][1].x * Ddiag[tid * 4 + 2] +
                         rho[2][2].x * Ddiag[tid * 4 + 3]);
        const int oi[6] = {1, 2, 2, 3, 3, 3};
        const int oj[6] = {0, 0, 1, 0, 1, 2};
#pragma unroll
        for (int c = 0; c < 6; c++) {
            float Av = Aoff[tid * 6 + c], Bv = Boff[tid * 6 + c];
            float2 rji = rho[oj[c]][oi[c]];
            q += 2.f * (rji.x * Av - rji.y * Bv);
        }
        g_q[b * 16 + tid] = q;
    }
}

// ------------------- vel head layer 1 (K=15, tiny) --------------------------
__global__ void k_vel1(const float* __restrict__ Wv1, const float* __restrict__ bv1)
{
    int b = blockIdx.x, t = threadIdx.x;
    __shared__ float qs[15];
    if (t < 15) qs[t] = g_q[b * 16 + t];
    __syncthreads();
    float acc = bv1[t];
#pragma unroll
    for (int w = 0; w < 15; w++) acc += qs[w] * Wv1[w * 256 + t];
    g_h2[b * 256 + t] = silu_f(acc);
}

// ------------------- launch ---------------------------------------------------
extern "C" void kernel_launch(void* const* d_in, const int* in_sizes, int n_in,
                              void* d_out, int out_size)
{
    const float* x    = (const float*)d_in[0];
    const float* W1   = (const float*)d_in[1];
    const float* b1   = (const float*)d_in[2];
    const float* W2   = (const float*)d_in[3];
    const float* b2   = (const float*)d_in[4];
    const float* Aoff = (const float*)d_in[5];
    const float* Boff = (const float*)d_in[6];
    const float* Ddiag= (const float*)d_in[7];
    const float* Wv1  = (const float*)d_in[8];
    const float* bv1  = (const float*)d_in[9];
    const float* Wv2  = (const float*)d_in[10];
    const float* bv2  = (const float*)d_in[11];
    // d_in[12] (pauli) unused: structure exploited analytically
    float* out = (float*)d_out;

    float *p_h, *p_theta, *p_W2p, *p_h2;
    cudaGetSymbolAddress((void**)&p_h, g_h);
    cudaGetSymbolAddress((void**)&p_theta, g_theta);
    cudaGetSymbolAddress((void**)&p_W2p, g_W2p);
    cudaGetSymbolAddress((void**)&p_h2, g_h2);

    k_pad<<<(256 * 4096 + 255) / 256, 256>>>(W2);

    // enc layer 1: (512x768)@(768x256) + b1, silu
    sgemm64<<<dim3(4, 8), 256>>>(x, W1, p_h, 768, 768, 256, 256, b1, 256, 1);
    // enc layer 2: (512x256)@(256x4096p) + b2
    sgemm64<<<dim3(64, 8), 256>>>(p_h, p_W2p, p_theta, 256, 256, 4096, 4096, b2, NGEN, 0);

    k_buildH<<<BATCH, 256>>>();
    k_expm<<<BATCH, 128>>>(Aoff, Boff, Ddiag);
    k_vel1<<<BATCH, 256>>>(Wv1, bv1);

    // vel layer 2: (512x256)@(256x512) + bv2
    sgemm64<<<dim3(8, 8), 256>>>(p_h2, Wv2, out, 256, 256, 512, 512, bv2, 512, 0);

    (void)in_sizes; (void)n_in; (void)out_size;
}

// round 3
// speedup vs baseline: 2.4989x; 2.4989x over previous
#include <cuda_runtime.h>
#include <math.h>
#include <stdint.h>

#define BATCH 512
#define NGEN  4095

// ------------------- scratch (static device globals; no allocs) -------------
__device__ float g_h[BATCH * 256];        // hidden after enc layer 1
__device__ float g_theta[BATCH * 4096];   // angles (row stride 4096, col 4095 = 0)
__device__ float g_W2p[256 * 4096];       // padded W2
__device__ float g_q[BATCH * 16];         // 15 expectations
__device__ float g_h2[BATCH * 256];       // hidden of vel head

__constant__ int c_wa[15] = {0,0,0,0,0,1,1,1,1,2,2,2,3,3,4};
__constant__ int c_wb[15] = {1,2,3,4,5,2,3,4,5,3,4,5,4,5,5};
__constant__ float c_inv[28] = {
    0.f, 1.f, 1.f/2, 1.f/3, 1.f/4, 1.f/5, 1.f/6, 1.f/7, 1.f/8, 1.f/9,
    1.f/10, 1.f/11, 1.f/12, 1.f/13, 1.f/14, 1.f/15, 1.f/16, 1.f/17,
    1.f/18, 1.f/19, 1.f/20, 1.f/21, 1.f/22, 1.f/23, 1.f/24, 1.f/25,
    1.f/26, 1.f/27};

#define NTERMS 27
#define THMAX  6.6f

__device__ __forceinline__ float silu_f(float x) { return x / (1.f + expf(-x)); }

// spread bit k of x to bit 2k
__device__ __forceinline__ int sp2(int x) {
    return (x & 1) | ((x & 2) << 1) | ((x & 4) << 2) |
           ((x & 8) << 3) | ((x & 16) << 4) | ((x & 32) << 5);
}

// ------------------- pad W2 (256 x 4095 -> 256 x 4096) ----------------------
__global__ void k_pad(const float* __restrict__ W2) {
    int idx = blockIdx.x * blockDim.x + threadIdx.x;
    if (idx < 256 * 4096) {
        int col = idx & 4095;
        int row = idx >> 12;
        g_W2p[idx] = (col < NGEN) ? W2[row * NGEN + col] : 0.f;
    }
}

// ------------------- tiled SGEMM 64x64x16 (small layers) --------------------
__global__ void sgemm64(const float* __restrict__ A, const float* __restrict__ B,
                        float* __restrict__ C, int K, int lda, int ldb, int ldc,
                        const float* __restrict__ bias, int nbias, int act)
{
    __shared__ float As[16][64];
    __shared__ float Bs[16][64];
    int tid = threadIdx.x;
    int bm = blockIdx.y * 64, bn = blockIdx.x * 64;
    int tx = tid & 15, ty = tid >> 4;

    int arow = tid >> 2;
    int akq  = (tid & 3) * 4;
    int brow = tid >> 4;
    int bcol = (tid & 15) * 4;

    float acc[4][4] = {};

    for (int k0 = 0; k0 < K; k0 += 16) {
        float4 av = *reinterpret_cast<const float4*>(A + (size_t)(bm + arow) * lda + k0 + akq);
        float4 bv = *reinterpret_cast<const float4*>(B + (size_t)(k0 + brow) * ldb + bn + bcol);
        As[akq + 0][arow] = av.x;
        As[akq + 1][arow] = av.y;
        As[akq + 2][arow] = av.z;
        As[akq + 3][arow] = av.w;
        *reinterpret_cast<float4*>(&Bs[brow][bcol]) = bv;
        __syncthreads();
#pragma unroll
        for (int k = 0; k < 16; k++) {
            float4 a = *reinterpret_cast<float4*>(&As[k][ty * 4]);
            float4 bq = *reinterpret_cast<float4*>(&Bs[k][tx * 4]);
            float ar[4] = {a.x, a.y, a.z, a.w};
            float br[4] = {bq.x, bq.y, bq.z, bq.w};
#pragma unroll
            for (int i = 0; i < 4; i++)
#pragma unroll
                for (int j = 0; j < 4; j++)
                    acc[i][j] += ar[i] * br[j];
        }
        __syncthreads();
    }

#pragma unroll
    for (int i = 0; i < 4; i++) {
        int row = bm + ty * 4 + i;
        int col = bn + tx * 4;
        float o[4];
#pragma unroll
        for (int j = 0; j < 4; j++) {
            float v = acc[i][j];
            int cj = col + j;
            v += (cj < nbias) ? bias[cj] : 0.f;
            if (act) v = silu_f(v);
            o[j] = v;
        }
        *reinterpret_cast<float4*>(&C[(size_t)row * ldc + col]) =
            make_float4(o[0], o[1], o[2], o[3]);
    }
}

// ------------------- tiled SGEMM 128x128x16, 8x8 microtile ------------------
__global__ void __launch_bounds__(256) sgemm128(
    const float* __restrict__ A, const float* __restrict__ B,
    float* __restrict__ C, int K, int lda, int ldb, int ldc,
    const float* __restrict__ bias, int nbias, int act)
{
    __shared__ float As[16][132];   // padded to dodge bank conflicts on store
    __shared__ float Bs[16][128];
    int tid = threadIdx.x;
    int bm = blockIdx.y * 128, bn = blockIdx.x * 128;
    int tx = tid & 15, ty = tid >> 4;

    int arow = tid >> 1;
    int ak   = (tid & 1) * 8;
    int brow = tid >> 4;
    int bcol = (tid & 15) * 8;

    float acc[8][8] = {};

    for (int k0 = 0; k0 < K; k0 += 16) {
        float4 a0 = *reinterpret_cast<const float4*>(A + (size_t)(bm + arow) * lda + k0 + ak);
        float4 a1 = *reinterpret_cast<const float4*>(A + (size_t)(bm + arow) * lda + k0 + ak + 4);
        float4 b0 = *reinterpret_cast<const float4*>(B + (size_t)(k0 + brow) * ldb + bn + bcol);
        float4 b1 = *reinterpret_cast<const float4*>(B + (size_t)(k0 + brow) * ldb + bn + bcol + 4);
        As[ak + 0][arow] = a0.x; As[ak + 1][arow] = a0.y;
        As[ak + 2][arow] = a0.z; As[ak + 3][arow] = a0.w;
        As[ak + 4][arow] = a1.x; As[ak + 5][arow] = a1.y;
        As[ak + 6][arow] = a1.z; As[ak + 7][arow] = a1.w;
        *reinterpret_cast<float4*>(&Bs[brow][bcol])     = b0;
        *reinterpret_cast<float4*>(&Bs[brow][bcol + 4]) = b1;
        __syncthreads();
#pragma unroll
        for (int k = 0; k < 16; k++) {
            float4 av0 = *reinterpret_cast<float4*>(&As[k][ty * 8]);
            float4 av1 = *reinterpret_cast<float4*>(&As[k][ty * 8 + 4]);
            float4 bv0 = *reinterpret_cast<float4*>(&Bs[k][tx * 8]);
            float4 bv1 = *reinterpret_cast<float4*>(&Bs[k][tx * 8 + 4]);
            float ar[8] = {av0.x, av0.y, av0.z, av0.w, av1.x, av1.y, av1.z, av1.w};
            float br[8] = {bv0.x, bv0.y, bv0.z, bv0.w, bv1.x, bv1.y, bv1.z, bv1.w};
#pragma unroll
            for (int i = 0; i < 8; i++)
#pragma unroll
                for (int j = 0; j < 8; j++)
                    acc[i][j] = fmaf(ar[i], br[j], acc[i][j]);
        }
        __syncthreads();
    }

#pragma unroll
    for (int i = 0; i < 8; i++) {
        int row = bm + ty * 8 + i;
#pragma unroll
        for (int jq = 0; jq < 2; jq++) {
            int col = bn + tx * 8 + jq * 4;
            float o[4];
#pragma unroll
            for (int j = 0; j < 4; j++) {
                float v = acc[i][jq * 4 + j];
                int cj = col + j;
                v += (cj < nbias) ? bias[cj] : 0.f;
                if (act) v = silu_f(v);
                o[j] = v;
            }
            *reinterpret_cast<float4*>(&C[(size_t)row * ldc + col]) =
                make_float4(o[0], o[1], o[2], o[3]);
        }
    }
}

// ------------------- fused buildH (Kronecker transform) + expm + obs --------
// 64 threads, one full 64-complex row of H per thread in registers.
__global__ void __launch_bounds__(64) k_expm2(const float* __restrict__ Aoff,
                                              const float* __restrict__ Boff,
                                              const float* __restrict__ Ddiag)
{
    __shared__ float2 sV[4096];    // 32KB: Pauli-coeff transform workspace
    __shared__ float  sred[2];
    __shared__ int    sh_s;
    __shared__ float  sh_sc;

    int b = blockIdx.x, tid = threadIdx.x;   // tid = row r

    // ---- load theta as word-coefficients: sV[w] = theta[w-1], sV[0]=0 ----
    const float* th = &g_theta[(size_t)b * 4096];
    float ssq = 0.f;
    for (int j = tid; j < 4095; j += 64) {
        float v = th[j];
        ssq += v * v;
        sV[j + 1] = make_float2(v, 0.f);
    }
    if (tid == 0) sV[0] = make_float2(0.f, 0.f);
#pragma unroll
    for (int o = 16; o; o >>= 1) ssq += __shfl_xor_sync(0xffffffffu, ssq, o);
    if ((tid & 31) == 0) sred[tid >> 5] = ssq;

    // ---- 6 butterfly stages: digit q -> (i_q, j_q) ----
    for (int q = 0; q < 6; q++) {
        __syncthreads();
        if (q == 0 && tid == 0) {
            float fro = 8.f * sqrtf(sred[0] + sred[1]);   // ||H||_F >= ||H||_2
            int e = 0;
            while (fro > THMAX && e < 16) { fro *= 0.5f; e++; }
            sh_s = e;
            sh_sc = ldexpf(1.f, -e);
        }
        int p = 10 - 2 * q;
        int mlow = (1 << p) - 1;
        for (int g = tid; g < 1024; g += 64) {
            int base = ((g >> p) << (p + 2)) | (g & mlow);
            float2 cI = sV[base];
            float2 cX = sV[base | (1 << p)];
            float2 cY = sV[base | (2 << p)];
            float2 cZ = sV[base | (3 << p)];
            sV[base]            = make_float2(cI.x + cZ.x, cI.y + cZ.y);
            sV[base | (1 << p)] = make_float2(cX.x + cY.y, cX.y - cY.x);  // cX - i*cY
            sV[base | (2 << p)] = make_float2(cX.x - cY.y, cX.y + cY.x);  // cX + i*cY
            sV[base | (3 << p)] = make_float2(cI.x - cZ.x, cI.y - cZ.y);
        }
    }
    __syncthreads();

    // ---- each thread loads its H row: H[r][c] = sV[(sp2(r)<<1)|sp2(c)] ----
    float2 h[64];
    int spr = sp2(tid) << 1;
#pragma unroll
    for (int c = 0; c < 64; c++) h[c] = sV[spr | sp2(c)];
    __syncthreads();   // all reads of sV done; safe to reuse as state buffers

    float2* ts0 = sV;
    float2* ts1 = sV + 64;
    float2* ps  = sV + 128;

    int S = sh_s;
    float sc = sh_sc;
    int nstep = 1 << S;

    float2 v = make_float2((tid == 0) ? 1.f : 0.f, 0.f);  // e0

    for (int step = 0; step < nstep; ++step) {
        float2 w = v;
        ts0[tid] = v;
        __syncthreads();
        const float2* tsrc = ts0;
        float2* tdst = ts1;
#pragma unroll 1
        for (int n = 1; n <= NTERMS; ++n) {
            float ux = 0.f, uy = 0.f, ux2 = 0.f, uy2 = 0.f;
            const float4* tp = reinterpret_cast<const float4*>(tsrc);
#pragma unroll
            for (int c = 0; c < 32; c++) {
                float4 t4 = tp[c];
                float2 a = h[2 * c];
                ux  = fmaf(a.x, t4.x, ux);  ux  = fmaf(-a.y, t4.y, ux);
                uy  = fmaf(a.x, t4.y, uy);  uy  = fmaf(a.y, t4.x, uy);
                a = h[2 * c + 1];
                ux2 = fmaf(a.x, t4.z, ux2); ux2 = fmaf(-a.y, t4.w, ux2);
                uy2 = fmaf(a.x, t4.w, uy2); uy2 = fmaf(a.y, t4.z, uy2);
            }
            ux += ux2; uy += uy2;
            float f = sc * c_inv[n];
            float2 tn = make_float2(-uy * f, ux * f);   // (i*u)*f
            w.x += tn.x; w.y += tn.y;
            tdst[tid] = tn;
            __syncthreads();
            const float2* tmp = tsrc; tsrc = tdst; tdst = const_cast<float2*>(tmp);
        }
        v = w;
    }
    ps[tid] = v;   // psi
    __syncthreads();

    // ---- 15 two-local expectations, one thread each ----
    if (tid < 15) {
        int wa = c_wa[tid], wb = c_wb[tid];
        int pa = 5 - wa, pb = 5 - wb;
        float2 rho[4][4];
#pragma unroll
        for (int k = 0; k < 4; k++)
#pragma unroll
            for (int l = 0; l < 4; l++) rho[k][l] = make_float2(0.f, 0.f);

        for (int r = 0; r < 16; r++) {
            int base = 0, t = 3;
            for (int p = 5; p >= 0; --p) {
                if (p == pa || p == pb) continue;
                if ((r >> t) & 1) base |= 1 << p;
                t--;
            }
            float2 pv[4];
#pragma unroll
            for (int k = 0; k < 4; k++) {
                int p = base | ((k >> 1) << pa) | ((k & 1) << pb);
                pv[k] = ps[p];
            }
#pragma unroll
            for (int k = 0; k < 4; k++)
#pragma unroll
                for (int l = 0; l < 4; l++) {
                    rho[k][l].x += pv[k].x * pv[l].x + pv[k].y * pv[l].y;
                    rho[k][l].y += pv[k].y * pv[l].x - pv[k].x * pv[l].y;
                }
        }
        float q = 2.f * (rho[0][0].x * Ddiag[tid * 4 + 1] +
                         rho[1][1].x * Ddiag[tid * 4 + 2] +
                         rho[2][2].x * Ddiag[tid * 4 + 3]);
        const int oi[6] = {1, 2, 2, 3, 3, 3};
        const int oj[6] = {0, 0, 1, 0, 1, 2};
#pragma unroll
        for (int c = 0; c < 6; c++) {
            float Av = Aoff[tid * 6 + c], Bv = Boff[tid * 6 + c];
            float2 rji = rho[oj[c]][oi[c]];
            q += 2.f * (rji.x * Av - rji.y * Bv);
        }
        g_q[b * 16 + tid] = q;
    }
}

// ------------------- vel head layer 1 (K=15, tiny) --------------------------
__global__ void k_vel1(const float* __restrict__ Wv1, const float* __restrict__ bv1)
{
    int b = blockIdx.x, t = threadIdx.x;
    __shared__ float qs[15];
    if (t < 15) qs[t] = g_q[b * 16 + t];
    __syncthreads();
    float acc = bv1[t];
#pragma unroll
    for (int w = 0; w < 15; w++) acc += qs[w] * Wv1[w * 256 + t];
    g_h2[b * 256 + t] = silu_f(acc);
}

// ------------------- launch ---------------------------------------------------
extern "C" void kernel_launch(void* const* d_in, const int* in_sizes, int n_in,
                              void* d_out, int out_size)
{
    const float* x    = (const float*)d_in[0];
    const float* W1   = (const float*)d_in[1];
    const float* b1   = (const float*)d_in[2];
    const float* W2   = (const float*)d_in[3];
    const float* b2   = (const float*)d_in[4];
    const float* Aoff = (const float*)d_in[5];
    const float* Boff = (const float*)d_in[6];
    const float* Ddiag= (const float*)d_in[7];
    const float* Wv1  = (const float*)d_in[8];
    const float* bv1  = (const float*)d_in[9];
    const float* Wv2  = (const float*)d_in[10];
    const float* bv2  = (const float*)d_in[11];
    float* out = (float*)d_out;

    float *p_h, *p_theta, *p_W2p, *p_h2;
    cudaGetSymbolAddress((void**)&p_h, g_h);
    cudaGetSymbolAddress((void**)&p_theta, g_theta);
    cudaGetSymbolAddress((void**)&p_W2p, g_W2p);
    cudaGetSymbolAddress((void**)&p_h2, g_h2);

    k_pad<<<(256 * 4096 + 255) / 256, 256>>>(W2);

    // enc layer 1: (512x768)@(768x256) + b1, silu
    sgemm64<<<dim3(4, 8), 256>>>(x, W1, p_h, 768, 768, 256, 256, b1, 256, 1);
    // enc layer 2: (512x256)@(256x4096p) + b2  -> theta
    sgemm128<<<dim3(32, 4), 256>>>(p_h, p_W2p, p_theta, 256, 256, 4096, 4096, b2, NGEN, 0);

    // fused buildH + expm(iH)e0 + observables
    k_expm2<<<BATCH, 64>>>(Aoff, Boff, Ddiag);

    k_vel1<<<BATCH, 256>>>(Wv1, bv1);

    // vel layer 2: (512x256)@(256x512) + bv2
    sgemm64<<<dim3(8, 8), 256>>>(p_h2, Wv2, out, 256, 256, 512, 512, bv2, 512, 0);

    (void)in_sizes; (void)n_in; (void)out_size;
}